// round 4
// baseline (speedup 1.0000x reference)
#include <cuda_runtime.h>
#include <cuda_bf16.h>
#include <cstdint>
#include <cstddef>

// ============================================================================
// out[16384,2048] = (x @ W^T) * (1/sqrt(2048)) + 0.1*b
// tcgen05 path (sm_103a pass): double-bf16 split (hi+lo) -> 3 accumulating
// bf16 MMAs per k-step; cp.async.bulk 2-stage pipeline; TMEM accumulators.
// Fallback path (plain sm_103 pass): SIMT fp32 GEMM, same launch config.
// ============================================================================

// Arch-specific (".a") feature gate: tcgen05 only exists in sm_10xa passes.
#if defined(__CUDA_ARCH_FEAT_SM103_ALL) || defined(__CUDA_ARCH_FEAT_SM100_ALL) \
 || defined(__CUDA_ARCH_FEAT_SM101_ALL) \
 || (defined(__CUDA_ARCH_SPECIFIC__) && (__CUDA_ARCH_SPECIFIC__ >= 1000)) \
 || (defined(__CUDA_ARCH_FAMILY_SPECIFIC__) && (__CUDA_ARCH_FAMILY_SPECIFIC__ >= 1000))
#define HAS_TCGEN05 1
#else
#define HAS_TCGEN05 0
#endif

#define N_ROWS 16384
#define D_IN   2048
#define D_OUT  2048

#define TM 128
#define TN 256
#define KC 64                       // K elements per stage (128B bf16 rows, SW128)
#define NKT (D_IN / KC)             // 32 K-iterations
#define KSTEPS (KC / 16)            // 4 MMA k-steps per iteration

#define A_TILE_BYTES (2 * TM * KC * 2)   // hi+lo A tile: 32768 B
#define B_TILE_BYTES (2 * TN * KC * 2)   // hi+lo B tile: 65536 B
#define STAGE_BYTES  (A_TILE_BYTES + B_TILE_BYTES)  // 98304 B

#define SMEM_TMEMPTR 0
#define SMEM_BAR     64
#define SMEM_STAGE0  1024
#define SMEM_TOTAL   (SMEM_STAGE0 + 2 * STAGE_BYTES)  // 197632 B

#define TMEM_COLS 256

// idesc kind::f16: F32 acc (bit4), BF16 a (bit7), BF16 b (bit10), N=128, M=128
#define MMA_IDESC ((1u << 4) | (1u << 7) | (1u << 10) | ((128u / 8u) << 17) | ((128u / 16u) << 24))

// ---------------- scratch (device globals: allocation-free) ----------------
__device__ __align__(128) unsigned char g_X[(size_t)(N_ROWS / TM) * NKT * A_TILE_BYTES]; // 128 MB
__device__ __align__(128) unsigned char g_W[(size_t)(D_OUT / TN) * NKT * B_TILE_BYTES];  // 16 MB

// ---------------- helpers (portable: mbarrier / bulk-copy are sm_90+) ------
__device__ __forceinline__ uint32_t smem_u32(const void* p) {
    uint32_t a;
    asm("{ .reg .u64 t; cvta.to.shared.u64 t, %1; cvt.u32.u64 %0, t; }" : "=r"(a) : "l"(p));
    return a;
}

__device__ __forceinline__ void mbar_init(uint32_t mbar, uint32_t count) {
    asm volatile("mbarrier.init.shared.b64 [%0], %1;" :: "r"(mbar), "r"(count) : "memory");
}

__device__ __forceinline__ void mbar_expect_tx(uint32_t mbar, uint32_t bytes) {
    asm volatile("mbarrier.arrive.expect_tx.shared.b64 _, [%0], %1;"
                 :: "r"(mbar), "r"(bytes) : "memory");
}

__device__ __forceinline__ void mbar_wait(uint32_t mbar, uint32_t parity) {
    asm volatile(
        "{\n\t"
        ".reg .pred P;\n\t"
        "WAIT_%=:\n\t"
        "mbarrier.try_wait.parity.acquire.cta.shared::cta.b64 P, [%0], %1, 0x989680;\n\t"
        "@!P bra WAIT_%=;\n\t"
        "}\n"
        :: "r"(mbar), "r"(parity) : "memory");
}

__device__ __forceinline__ void bulk_g2s(uint32_t dst_smem, const void* src_gmem,
                                         uint32_t bytes, uint32_t mbar) {
    asm volatile(
        "cp.async.bulk.shared::cluster.global.mbarrier::complete_tx::bytes [%0], [%1], %2, [%3];"
        :: "r"(dst_smem), "l"(src_gmem), "r"(bytes), "r"(mbar) : "memory");
}

// 64-bit SMEM matrix descriptor, SW128, Blackwell (LBO=1, SBO=64)
__device__ __forceinline__ uint64_t make_desc(uint32_t smem_addr) {
    const uint64_t BASE = (uint64_t(2) << 61)
                        | (uint64_t(1) << 46)
                        | (uint64_t(64) << 32)
                        | (uint64_t(1) << 16);
    return BASE | ((uint64_t)(smem_addr >> 4) & 0x3FFF);
}

#if HAS_TCGEN05
// ---------------- tcgen05 wrappers (only emitted in the 'a' pass) ----------
__device__ __forceinline__ void mma_f16_ss(uint32_t d_tmem, uint64_t a_desc, uint64_t b_desc,
                                           uint32_t en) {
    asm volatile(
        "{\n\t"
        ".reg .pred p;\n\t"
        "setp.ne.u32 p, %5, 0;\n\t"
        "tcgen05.mma.cta_group::1.kind::f16 [%0], %1, %2, %3, {%4, %4, %4, %4}, p;\n\t"
        "}"
        :: "r"(d_tmem), "l"(a_desc), "l"(b_desc), "r"(MMA_IDESC), "r"(0u), "r"(en)
        : "memory");
}

__device__ __forceinline__ void tcommit(uint32_t mbar) {
    asm volatile("tcgen05.commit.cta_group::1.mbarrier::arrive::one.shared::cluster.b64 [%0];"
                 :: "r"(mbar) : "memory");
}

#define TLD_32X32B_X32(r, tmem_addr) \
    asm volatile( \
        "tcgen05.ld.sync.aligned.32x32b.x32.b32 " \
        "{%0, %1, %2, %3, %4, %5, %6, %7, " \
        " %8, %9, %10, %11, %12, %13, %14, %15, " \
        " %16, %17, %18, %19, %20, %21, %22, %23, " \
        " %24, %25, %26, %27, %28, %29, %30, %31}, [%32];" \
        : "=r"((r)[0]),  "=r"((r)[1]),  "=r"((r)[2]),  "=r"((r)[3]), \
          "=r"((r)[4]),  "=r"((r)[5]),  "=r"((r)[6]),  "=r"((r)[7]), \
          "=r"((r)[8]),  "=r"((r)[9]),  "=r"((r)[10]), "=r"((r)[11]), \
          "=r"((r)[12]), "=r"((r)[13]), "=r"((r)[14]), "=r"((r)[15]), \
          "=r"((r)[16]), "=r"((r)[17]), "=r"((r)[18]), "=r"((r)[19]), \
          "=r"((r)[20]), "=r"((r)[21]), "=r"((r)[22]), "=r"((r)[23]), \
          "=r"((r)[24]), "=r"((r)[25]), "=r"((r)[26]), "=r"((r)[27]), \
          "=r"((r)[28]), "=r"((r)[29]), "=r"((r)[30]), "=r"((r)[31]) \
        : "r"(tmem_addr))
#endif  // HAS_TCGEN05

// ============================================================================
// Conversion: fp32 -> per-(row_tile, k_tile) [hi | lo] bf16 tiles, SW128
// swizzled so the GEMM bulk-copies straight into SMEM for MMA descriptors.
// (Arch-portable; used only by the tcgen05 path but harmless otherwise.)
// ============================================================================
template <int TILE_R>
__global__ void __launch_bounds__(256) convert_kernel(const float* __restrict__ src) {
    unsigned char* dstBase = (TILE_R == 128) ? g_X : g_W;
    const int tk = blockIdx.x;
    const int tr = blockIdx.y;
    const size_t tileBytes = (size_t)TILE_R * KC * 2;
    unsigned char* hi = dstBase + (size_t)(tr * NKT + tk) * 2 * tileBytes;
    unsigned char* lo = hi + tileBytes;
    const int pairs = TILE_R * (KC / 2);
    for (int i = threadIdx.x; i < pairs; i += blockDim.x) {
        const int r = i >> 5;
        const int p = i & 31;
        const float2 v = *(const float2*)(src + (size_t)(tr * TILE_R + r) * D_IN + tk * KC + p * 2);
        const __nv_bfloat16 h0 = __float2bfloat16(v.x);
        const __nv_bfloat16 h1 = __float2bfloat16(v.y);
        const __nv_bfloat16 l0 = __float2bfloat16(v.x - __bfloat162float(h0));
        const __nv_bfloat16 l1 = __float2bfloat16(v.y - __bfloat162float(h1));
        const uint32_t off = (uint32_t)r * 128u + (uint32_t)p * 4u;
        const uint32_t sw = off ^ ((off >> 3) & 0x70);
        const uint32_t hp = ((uint32_t)__bfloat16_as_ushort(h1) << 16) | __bfloat16_as_ushort(h0);
        const uint32_t lp = ((uint32_t)__bfloat16_as_ushort(l1) << 16) | __bfloat16_as_ushort(l0);
        *(uint32_t*)(hi + sw) = hp;
        *(uint32_t*)(lo + sw) = lp;
    }
}

// ============================================================================
// GEMM kernel. Same launch config for both bodies:
//   grid (D_OUT/TN, N_ROWS/TM), block 128, dyn smem SMEM_TOTAL.
// ============================================================================
__global__ void __launch_bounds__(128, 1) gemm_kernel(const float* __restrict__ x,
                                                      const float* __restrict__ w,
                                                      const float* __restrict__ bias,
                                                      float* __restrict__ out) {
#if HAS_TCGEN05
    (void)x; (void)w;
    extern __shared__ __align__(1024) unsigned char smem[];
    const uint32_t sb = smem_u32(smem);
    const int tid = threadIdx.x;
    const int wid = tid >> 5, lid = tid & 31;
    const int tn = blockIdx.x;
    const int tm = blockIdx.y;

    if (tid == 0) {
        #pragma unroll
        for (int i = 0; i < 5; i++) mbar_init(sb + SMEM_BAR + i * 8, 1);
        asm volatile("fence.proxy.async.shared::cta;" ::: "memory");
    }
    if (wid == 0) {
        asm volatile("tcgen05.alloc.cta_group::1.sync.aligned.shared::cta.b32 [%0], %1;"
                     :: "r"(sb + SMEM_TMEMPTR), "r"(TMEM_COLS) : "memory");
    }
    __syncthreads();
    uint32_t tmem;
    asm volatile("ld.shared.b32 %0, [%1];" : "=r"(tmem) : "r"(sb + SMEM_TMEMPTR));
    if (wid == 0)
        asm volatile("tcgen05.relinquish_alloc_permit.cta_group::1.sync.aligned;");

    if (tid == 0) {
        const unsigned char* aSrc = g_X + (size_t)tm * NKT * A_TILE_BYTES;
        const unsigned char* bSrc = g_W + (size_t)tn * NKT * B_TILE_BYTES;

        #pragma unroll
        for (int s = 0; s < 2; s++) {
            const uint32_t fb = sb + SMEM_BAR + s * 8;
            const uint32_t st = sb + SMEM_STAGE0 + s * STAGE_BYTES;
            mbar_expect_tx(fb, STAGE_BYTES);
            bulk_g2s(st, aSrc + (size_t)s * A_TILE_BYTES, A_TILE_BYTES, fb);
            bulk_g2s(st + A_TILE_BYTES, bSrc + (size_t)s * B_TILE_BYTES, B_TILE_BYTES, fb);
        }

        int fullPh[2] = {0, 0}, emptyPh[2] = {0, 0};
        for (int kt = 0; kt < NKT; kt++) {
            const int s = kt & 1;
            const uint32_t fb = sb + SMEM_BAR + s * 8;
            const uint32_t eb = sb + SMEM_BAR + 16 + s * 8;
            mbar_wait(fb, fullPh[s]); fullPh[s] ^= 1;

            const uint32_t st = sb + SMEM_STAGE0 + s * STAGE_BYTES;
            const uint64_t dAhi = make_desc(st);
            const uint64_t dAlo = make_desc(st + A_TILE_BYTES / 2);
            const uint64_t dBhi = make_desc(st + A_TILE_BYTES);
            const uint64_t dBlo = make_desc(st + A_TILE_BYTES + B_TILE_BYTES / 2);
            const uint64_t NH = 1024;  // +128 B-rows = 16384 B / 16

            #pragma unroll
            for (int ks = 0; ks < KSTEPS; ks++) {
                const uint64_t ko = (uint64_t)(ks * 2);
                const uint32_t acc = (kt | ks) ? 1u : 0u;
                mma_f16_ss(tmem,       dAhi + ko, dBhi + ko,      acc);
                mma_f16_ss(tmem + 128, dAhi + ko, dBhi + NH + ko, acc);
                mma_f16_ss(tmem,       dAhi + ko, dBlo + ko,      1u);
                mma_f16_ss(tmem + 128, dAhi + ko, dBlo + NH + ko, 1u);
                mma_f16_ss(tmem,       dAlo + ko, dBhi + ko,      1u);
                mma_f16_ss(tmem + 128, dAlo + ko, dBhi + NH + ko, 1u);
            }
            tcommit(eb);  // stage s free once these MMAs retire

            if (kt + 2 < NKT) {
                mbar_wait(eb, emptyPh[s]); emptyPh[s] ^= 1;
                const int j = kt + 2;
                mbar_expect_tx(fb, STAGE_BYTES);
                bulk_g2s(st, aSrc + (size_t)j * A_TILE_BYTES, A_TILE_BYTES, fb);
                bulk_g2s(st + A_TILE_BYTES, bSrc + (size_t)j * B_TILE_BYTES, B_TILE_BYTES, fb);
            }
        }
        tcommit(sb + SMEM_BAR + 32);  // final: all MMAs done
    }

    mbar_wait(sb + SMEM_BAR + 32, 0);
    asm volatile("tcgen05.fence::after_thread_sync;" ::: "memory");

    // ---- epilogue: TMEM -> XOR-swizzled SMEM -> coalesced GMEM ----
    const int r = wid * 32 + lid;
    uint32_t* epi = (uint32_t*)(smem + SMEM_STAGE0);   // 128 KB, stages dead
    #pragma unroll
    for (int cb = 0; cb < TN; cb += 32) {
        uint32_t regs[32];
        TLD_32X32B_X32(regs, tmem + cb);
        asm volatile("tcgen05.wait::ld.sync.aligned;" ::: "memory");
        #pragma unroll
        for (int j = 0; j < 32; j++) {
            const int c = cb + j;
            epi[r * TN + (c ^ (r & 31))] = regs[j];
        }
    }
    asm volatile("tcgen05.fence::before_thread_sync;" ::: "memory");
    __syncthreads();

    const float scale = 0.022097086912079608f;  // 1/sqrt(2048)
    float* outRow = out + (size_t)tm * TM * D_OUT + (size_t)tn * TN;
    const float* bch = bias + tn * TN;
    #pragma unroll 4
    for (int it = 0; it < (TM * TN) / 128; it++) {
        const int i = it * 128 + tid;
        const int rr = i >> 8;
        const int c = i & 255;
        const float v = __uint_as_float(epi[rr * TN + (c ^ (rr & 31))]);
        outRow[(size_t)rr * D_OUT + c] = v * scale + 0.1f * __ldg(bch + c);
    }

    __syncthreads();
    if (wid == 0)
        asm volatile("tcgen05.dealloc.cta_group::1.sync.aligned.b32 %0, %1;"
                     :: "r"(tmem), "r"(TMEM_COLS));

#else  // ======================= SIMT fp32 fallback =========================
    extern __shared__ __align__(16) float fsm[];
    float* ws = fsm;                 // 32 cols x 128 k  (16 KB)
    float* xs = fsm + 32 * 128;      // 128 rows x (128 k, pad to 132)  (66 KB)
    const int tid = threadIdx.x;
    const int tn = blockIdx.x, tm = blockIdx.y;
    const int row = tm * TM + tid;
    const float scale = 0.022097086912079608f;

    for (int nc = 0; nc < TN / 32; nc++) {
        const int cb = tn * TN + nc * 32;
        float acc[32];
        #pragma unroll
        for (int c = 0; c < 32; c++) acc[c] = 0.0f;

        for (int kb = 0; kb < D_IN; kb += 128) {
            __syncthreads();
            for (int i = tid; i < 32 * 128; i += 128)
                ws[i] = w[(size_t)(cb + (i >> 7)) * D_IN + kb + (i & 127)];
            for (int i = tid; i < 128 * 128; i += 128)
                xs[(i >> 7) * 132 + (i & 127)] = x[(size_t)(tm * TM + (i >> 7)) * D_IN + kb + (i & 127)];
            __syncthreads();

            #pragma unroll 2
            for (int k4 = 0; k4 < 32; k4++) {
                const float4 xv = *(const float4*)&xs[tid * 132 + k4 * 4];
                #pragma unroll
                for (int c = 0; c < 32; c++) {
                    const float4 wv = *(const float4*)&ws[(c << 7) + (k4 << 2)];
                    acc[c] += xv.x * wv.x + xv.y * wv.y + xv.z * wv.z + xv.w * wv.w;
                }
            }
        }
        #pragma unroll
        for (int c = 0; c < 32; c++)
            out[(size_t)row * D_OUT + cb + c] = acc[c] * scale + 0.1f * bias[cb + c];
    }
#endif
}

// ============================================================================
extern "C" void kernel_launch(void* const* d_in, const int* in_sizes, int n_in,
                              void* d_out, int out_size) {
    const float* x = (const float*)d_in[0];
    const float* w = (const float*)d_in[1];
    const float* b = (const float*)d_in[2];
    float* out = (float*)d_out;

    cudaFuncSetAttribute(gemm_kernel, cudaFuncAttributeMaxDynamicSharedMemorySize, SMEM_TOTAL);

    convert_kernel<128><<<dim3(NKT, N_ROWS / TM), 256>>>(x);   // x -> g_X (hi/lo, swizzled)
    convert_kernel<256><<<dim3(NKT, D_OUT / TN), 256>>>(w);    // W -> g_W
    gemm_kernel<<<dim3(D_OUT / TN, N_ROWS / TM), 128, SMEM_TOTAL>>>(x, w, b, out);
}